// round 12
// baseline (speedup 1.0000x reference)
#include <cuda_runtime.h>
#include <cuda_bf16.h>

// ---------------------------------------------------------------------------
// Problem constants (fixed by the reference)
// ---------------------------------------------------------------------------
#define CLOUDS   4
#define NPTS     16384
#define MCENT    4096            // RATIO * NPTS
#define MAXNB    64
#define R2       0.0625f         // 0.25^2
#define CLUSTER  16              // nonportable cluster size
#define PTS_PER_CTA (NPTS / CLUSTER)   // 1024
#define FPS_THREADS 256
#define PPT      4               // points per thread
#define PAIRS    (PPT / 2)
#define NWARPS   (FPS_THREADS / 32)    // 8

#define OUT_XC   0                      // x_centers  [16384*3]
#define OUT_POS  (CLOUDS*MCENT*3)       // pos[idx]   [16384*3]
#define OUT_BAT  (CLOUDS*MCENT*6)       // batch[idx] [16384]

// Device scratch (no cudaMalloc allowed)
__device__ float g_pos6[(size_t)CLOUDS * NPTS * 8];  // padded to 8 floats/pt
__device__ int   g_idx[CLOUDS * MCENT];

// ---------------------------------------------------------------------------
// f32x2 helpers (bit-exact packed math)
// ---------------------------------------------------------------------------
__device__ __forceinline__ unsigned long long pack2(float lo, float hi) {
    unsigned long long r;
    asm("mov.b64 %0, {%1, %2};" : "=l"(r) : "f"(lo), "f"(hi));
    return r;
}
__device__ __forceinline__ void unpack2(unsigned long long v,
                                        float& lo, float& hi) {
    asm("mov.b64 {%0, %1}, %2;" : "=f"(lo), "=f"(hi) : "l"(v));
}
__device__ __forceinline__ unsigned long long fma2(unsigned long long a,
                                                   unsigned long long b,
                                                   unsigned long long c) {
    unsigned long long r;
    asm("fma.rn.f32x2 %0, %1, %2, %3;"
        : "=l"(r) : "l"(a), "l"(b), "l"(c));
    return r;
}
__device__ __forceinline__ unsigned long long mul2(unsigned long long a,
                                                   unsigned long long b) {
    unsigned long long r;
    asm("mul.rn.f32x2 %0, %1, %2;" : "=l"(r) : "l"(a), "l"(b));
    return r;
}

// ---------------------------------------------------------------------------
// 6-D squared distance (scalar form for the neighbor kernel).
// FMA left fold matches XLA:GPU contraction of sum((p-c)**2, axis=-1).
// ---------------------------------------------------------------------------
__device__ __forceinline__ float dist6(float p0, float p1, float p2,
                                       float p3, float p4, float p5,
                                       float c0, float c1, float c2,
                                       float c3, float c4, float c5) {
    float t, d;
    t = __fsub_rn(p0, c0); d = __fmul_rn(t, t);
    t = __fsub_rn(p1, c1); d = __fmaf_rn(t, t, d);
    t = __fsub_rn(p2, c2); d = __fmaf_rn(t, t, d);
    t = __fsub_rn(p3, c3); d = __fmaf_rn(t, t, d);
    t = __fsub_rn(p4, c4); d = __fmaf_rn(t, t, d);
    t = __fsub_rn(p5, c5); d = __fmaf_rn(t, t, d);
    return d;
}

__device__ __forceinline__ unsigned redux_max_u32(unsigned v, unsigned mask) {
    unsigned r;
    asm("redux.sync.max.u32 %0, %1, %2;" : "=r"(r) : "r"(v), "r"(mask));
    return r;
}

// ---------------------------------------------------------------------------
// Kernel A: build padded pos6 = [x0 x1 x2 p0 p1 p2 0 0] per point
// ---------------------------------------------------------------------------
__global__ void prep_kernel(const float* __restrict__ x,
                            const float* __restrict__ pos) {
    int i = blockIdx.x * blockDim.x + threadIdx.x;
    if (i >= CLOUDS * NPTS) return;
    float4 r0 = make_float4(x[3 * i], x[3 * i + 1], x[3 * i + 2], pos[3 * i]);
    float4 r1 = make_float4(pos[3 * i + 1], pos[3 * i + 2], 0.f, 0.f);
    float4* dst = reinterpret_cast<float4*>(g_pos6);
    dst[2 * i] = r0;
    dst[2 * i + 1] = r1;
}

// ---------------------------------------------------------------------------
// Kernel B: FPS v9. 16-CTA cluster per cloud, 256 thr/CTA, 4 pts/thread.
// Pair-packed SoA f32x2 distance math (bit-exact per-lane fold).
// ALL 8 warps try_wait the mbarrier directly (no second __syncthreads),
// each resolves the 16 candidates into registers in parallel.
// Candidate record = 8 u32: {keybits, cloud_idx, c0,c1,c2,c3,c4,c5}.
// ---------------------------------------------------------------------------
__global__ void __launch_bounds__(FPS_THREADS, 1)
fps_kernel() {
    __shared__ unsigned long long mbar[2];
    __shared__ uint4 candbuf[2][CLUSTER][2];   // [parity][sender rank][32B]
    __shared__ unsigned slotkey[NWARPS];       // per-warp winner keybits
    __shared__ uint4 slotc[NWARPS][2];         // per-warp winner record

    unsigned rank;
    asm("mov.u32 %0, %%cluster_ctarank;" : "=r"(rank));
    const int cloud = blockIdx.x / CLUSTER;
    const int tid = threadIdx.x;
    const int wid = tid >> 5;
    const int lane = tid & 31;

    const float4* gp = reinterpret_cast<const float4*>(
        g_pos6 + (size_t)cloud * NPTS * 8);

    const int gbase = (int)rank * PTS_PER_CTA + tid * PPT;  // cloud-local

    // SoA pair packing: P[d][pr] = {dim d of pt 2pr, dim d of pt 2pr+1}
    unsigned long long P[6][PAIRS];
    float mind[PPT];
    const unsigned long long NEG1 = pack2(-1.0f, -1.0f);
#pragma unroll
    for (int pr = 0; pr < PAIRS; ++pr) {
        float4 e0 = gp[2 * (gbase + 2 * pr)],     e1 = gp[2 * (gbase + 2 * pr) + 1];
        float4 o0 = gp[2 * (gbase + 2 * pr + 1)], o1 = gp[2 * (gbase + 2 * pr + 1) + 1];
        P[0][pr] = pack2(e0.x, o0.x);
        P[1][pr] = pack2(e0.y, o0.y);
        P[2][pr] = pack2(e0.z, o0.z);
        P[3][pr] = pack2(e0.w, o0.w);
        P[4][pr] = pack2(e1.x, o1.x);
        P[5][pr] = pack2(e1.y, o1.y);
        mind[2 * pr] = __int_as_float(0x7f800000);
        mind[2 * pr + 1] = __int_as_float(0x7f800000);
    }

    // current winner coords; pick 0 = point 0 of the cloud
    float4 p0 = gp[0], p1 = gp[1];
    float w0 = p0.x, w1 = p0.y, w2 = p0.z, w3 = p0.w, w4 = p1.x, w5 = p1.y;

    if (tid == 0) {
        unsigned m0 = (unsigned)__cvta_generic_to_shared(&mbar[0]);
        unsigned m1 = (unsigned)__cvta_generic_to_shared(&mbar[1]);
        asm volatile("mbarrier.init.shared.b64 [%0], 1;" :: "r"(m0) : "memory");
        asm volatile("mbarrier.init.shared.b64 [%0], 1;" :: "r"(m1) : "memory");
        asm volatile("fence.mbarrier_init.release.cluster;" ::: "memory");
        if (rank == 0) g_idx[cloud * MCENT] = cloud * NPTS;
    }
    __syncthreads();
    // make mbarrier init visible cluster-wide before any peer st.async
    asm volatile("barrier.cluster.arrive.aligned;" ::: "memory");
    asm volatile("barrier.cluster.wait.aligned;"   ::: "memory");

    // loop-invariant peer addresses: lane i -> CTA i>>1, half (i&1)*16B
    unsigned dr0 = 0, dr1 = 0, mr0 = 0, mr1 = 0;
    if (wid == 0) {
        unsigned dst = (unsigned)(lane >> 1);
        unsigned half = (unsigned)(lane & 1) * 16u;
        unsigned dl0 = (unsigned)__cvta_generic_to_shared(&candbuf[0][rank][0]) + half;
        unsigned dl1 = (unsigned)__cvta_generic_to_shared(&candbuf[1][rank][0]) + half;
        unsigned ml0 = (unsigned)__cvta_generic_to_shared(&mbar[0]);
        unsigned ml1 = (unsigned)__cvta_generic_to_shared(&mbar[1]);
        asm("mapa.shared::cluster.u32 %0, %1, %2;" : "=r"(dr0) : "r"(dl0), "r"(dst));
        asm("mapa.shared::cluster.u32 %0, %1, %2;" : "=r"(dr1) : "r"(dl1), "r"(dst));
        asm("mapa.shared::cluster.u32 %0, %1, %2;" : "=r"(mr0) : "r"(ml0), "r"(dst));
        asm("mapa.shared::cluster.u32 %0, %1, %2;" : "=r"(mr1) : "r"(ml1), "r"(dst));
    }
    const unsigned mb0 = (unsigned)__cvta_generic_to_shared(&mbar[0]);
    const unsigned mb1 = (unsigned)__cvta_generic_to_shared(&mbar[1]);

    unsigned ph0 = 0, ph1 = 0;

#pragma unroll 1
    for (int k = 1; k < MCENT; ++k) {
        const int par = k & 1;
        if (tid == 0) {   // expected tx: 16 CTAs x 32 bytes
            asm volatile("mbarrier.arrive.expect_tx.shared.b64 _, [%0], %1;"
                         :: "r"(par ? mb1 : mb0), "r"(512u) : "memory");
        }
        // ---- packed-pair distances; thread-best (idx ascending, strict >) --
        const unsigned long long W0 = pack2(w0, w0);
        const unsigned long long W1 = pack2(w1, w1);
        const unsigned long long W2 = pack2(w2, w2);
        const unsigned long long W3 = pack2(w3, w3);
        const unsigned long long W4 = pack2(w4, w4);
        const unsigned long long W5 = pack2(w5, w5);
        unsigned bk = 0;
        unsigned bj = 0;
#pragma unroll
        for (int pr = 0; pr < PAIRS; ++pr) {
            unsigned long long T0 = fma2(W0, NEG1, P[0][pr]);
            unsigned long long T1 = fma2(W1, NEG1, P[1][pr]);
            unsigned long long T2 = fma2(W2, NEG1, P[2][pr]);
            unsigned long long T3 = fma2(W3, NEG1, P[3][pr]);
            unsigned long long T4 = fma2(W4, NEG1, P[4][pr]);
            unsigned long long T5 = fma2(W5, NEG1, P[5][pr]);
            unsigned long long D = mul2(T0, T0);
            D = fma2(T1, T1, D);
            D = fma2(T2, T2, D);
            D = fma2(T3, T3, D);
            D = fma2(T4, T4, D);
            D = fma2(T5, T5, D);
            float dlo, dhi;
            unpack2(D, dlo, dhi);
            mind[2 * pr] = fminf(mind[2 * pr], dlo);
            mind[2 * pr + 1] = fminf(mind[2 * pr + 1], dhi);
            unsigned k0 = __float_as_uint(mind[2 * pr]);
            if (k0 > bk) { bk = k0; bj = (unsigned)(2 * pr); }
            unsigned k1 = __float_as_uint(mind[2 * pr + 1]);
            if (k1 > bk) { bk = k1; bj = (unsigned)(2 * pr + 1); }
        }

        // ---- warp argmax: redux + ballot (lowest lane = lowest idx) ----
        unsigned m = redux_max_u32(bk, 0xffffffffu);
        unsigned bal = __ballot_sync(0xffffffffu, bk == m);
        if (lane == __ffs(bal) - 1) {
            // extract winning point's coords from SoA registers
            int pr = (int)(bj >> 1);
            bool hi = (bj & 1u) != 0;
            float c[6];
#pragma unroll
            for (int d = 0; d < 6; ++d) {
                float lo, h;
                unsigned long long v = P[d][0];
#pragma unroll
                for (int q = 1; q < PAIRS; ++q)
                    if (q == pr) v = P[d][q];
                unpack2(v, lo, h);
                c[d] = hi ? h : lo;
            }
            slotkey[wid] = m;
            slotc[wid][0] = make_uint4(m, (unsigned)(gbase + (int)bj),
                                       __float_as_uint(c[0]),
                                       __float_as_uint(c[1]));
            slotc[wid][1] = make_uint4(__float_as_uint(c[2]),
                                       __float_as_uint(c[3]),
                                       __float_as_uint(c[4]),
                                       __float_as_uint(c[5]));
        }
        __syncthreads();   // bar(1): 8 slots ready

        if (wid == 0) {
            // ---- CTA argmax over 8 warp slots (slot order = idx order) ----
            unsigned kw = slotkey[lane & (NWARPS - 1)];
            unsigned M = redux_max_u32(kw, 0xffffffffu);
            unsigned bb = __ballot_sync(0xffffffffu, kw == M);
            int s = __ffs(bb) - 1;          // lowest lane = lowest warp
            // all 32 lanes send one 16B half-record: lane i -> CTA i>>1
            const unsigned long long* src =
                reinterpret_cast<const unsigned long long*>(&slotc[s][0]);
            unsigned h = (unsigned)(lane & 1) * 2u;
            unsigned long long qa = src[h], qb = src[h + 1];
            unsigned dr = par ? dr1 : dr0;
            unsigned mr = par ? mr1 : mr0;
            asm volatile(
                "st.async.shared::cluster.mbarrier::complete_tx::bytes.v2.b64 [%0], {%1, %2}, [%3];"
                :: "r"(dr), "l"(qa), "l"(qb), "r"(mr) : "memory");
        }
        // ---- ALL warps wait for the 16 candidates (8 pollers) ----
        {
            unsigned mb = par ? mb1 : mb0;
            unsigned ph = par ? ph1 : ph0;
            unsigned done;
            do {
                asm volatile(
                    "{ .reg .pred p;\n\t"
                    "mbarrier.try_wait.parity.acquire.cta.shared::cta.b64 p, [%1], %2, 0x989680;\n\t"
                    "selp.b32 %0, 1, 0, p; }"
                    : "=r"(done) : "r"(mb), "r"(ph) : "memory");
            } while (!done);
            if (par) ph1 ^= 1; else ph0 ^= 1;
        }
        // ---- each warp resolves cluster winner into registers ----
        {
            unsigned kc = candbuf[par][lane & (CLUSTER - 1)][0].x;
            unsigned M2 = redux_max_u32(kc, 0xffffffffu);
            unsigned b2 = __ballot_sync(0xffffffffu, kc == M2);
            int s2 = __ffs(b2) - 1;          // lowest lane -> lowest rank
            uint4 r0 = candbuf[par][s2][0];
            uint4 r1 = candbuf[par][s2][1];
            w0 = __uint_as_float(r0.z); w1 = __uint_as_float(r0.w);
            w2 = __uint_as_float(r1.x); w3 = __uint_as_float(r1.y);
            w4 = __uint_as_float(r1.z); w5 = __uint_as_float(r1.w);
            if (rank == 0 && tid == 0)
                g_idx[cloud * MCENT + k] = cloud * NPTS + (int)r0.y;
        }
    }
}

// ---------------------------------------------------------------------------
// Kernel C: radius neighbors + mean.  One warp per center; ordered first-64
// take via ballot so capping matches top_k-on-index semantics exactly.
// ---------------------------------------------------------------------------
__global__ void __launch_bounds__(256)
nbr_kernel(float* __restrict__ out, int out_size) {
    int w = (blockIdx.x * blockDim.x + threadIdx.x) >> 5;
    int lane = threadIdx.x & 31;
    if (w >= CLOUDS * MCENT) return;
    int cloud = w >> 12;                 // 4096 centers per cloud
    int g = g_idx[w];
    int lc = g - cloud * NPTS;

    const float4* gp = reinterpret_cast<const float4*>(
        g_pos6 + (size_t)cloud * NPTS * 8);
    float4 c0 = gp[2 * lc], c1 = gp[2 * lc + 1];

    float sx = 0.f, sy = 0.f, sz = 0.f;
    int cnt = 0;
    for (int base = 0; base < NPTS; base += 32) {
        int i = base + lane;
        float4 a0 = gp[2 * i], a1 = gp[2 * i + 1];
        float d = dist6(a0.x, a0.y, a0.z, a0.w, a1.x, a1.y,
                        c0.x, c0.y, c0.z, c0.w, c1.x, c1.y);
        bool pred = (d <= R2);
        unsigned mask = __ballot_sync(0xffffffffu, pred);
        int need = MAXNB - cnt;
        int rk = __popc(mask & ((1u << lane) - 1u));
        if (pred && rk < need) { sx += a0.x; sy += a0.y; sz += a0.z; }
        int c = __popc(mask);
        cnt += (c < need) ? c : need;
        if (cnt >= MAXNB) break;         // warp-uniform
    }
#pragma unroll
    for (int s = 16; s > 0; s >>= 1) {
        sx += __shfl_down_sync(0xffffffffu, sx, s);
        sy += __shfl_down_sync(0xffffffffu, sy, s);
        sz += __shfl_down_sync(0xffffffffu, sz, s);
    }
    if (lane == 0) {
        float c = (float)cnt;            // self always in radius -> cnt >= 1
        if (OUT_XC + w * 3 + 2 < out_size) {
            out[OUT_XC + w * 3 + 0] = sx / c;
            out[OUT_XC + w * 3 + 1] = sy / c;
            out[OUT_XC + w * 3 + 2] = sz / c;
        }
    }
}

// ---------------------------------------------------------------------------
// Kernel D: gather pos[idx] and batch[idx]
// ---------------------------------------------------------------------------
__global__ void sample_kernel(const float* __restrict__ pos,
                              float* __restrict__ out, int out_size) {
    int c = blockIdx.x * blockDim.x + threadIdx.x;
    if (c >= CLOUDS * MCENT) return;
    int g = g_idx[c];
    if (OUT_POS + c * 3 + 2 < out_size) {
        out[OUT_POS + c * 3 + 0] = pos[3 * g + 0];
        out[OUT_POS + c * 3 + 1] = pos[3 * g + 1];
        out[OUT_POS + c * 3 + 2] = pos[3 * g + 2];
    }
    if (OUT_BAT + c < out_size)
        out[OUT_BAT + c] = (float)(g >> 14);   // batch id = g / NPTS
}

// ---------------------------------------------------------------------------
extern "C" void kernel_launch(void* const* d_in, const int* in_sizes, int n_in,
                              void* d_out, int out_size) {
    const float* x   = (const float*)d_in[0];
    const float* pos = (const float*)d_in[1];
    float* out = (float*)d_out;

    prep_kernel<<<(CLOUDS * NPTS + 255) / 256, 256>>>(x, pos);

    // FPS: 16-CTA clusters (nonportable size) via cudaLaunchKernelEx
    cudaFuncSetAttribute(fps_kernel,
                         cudaFuncAttributeNonPortableClusterSizeAllowed, 1);
    cudaLaunchConfig_t cfg = {};
    cfg.gridDim = dim3(CLOUDS * CLUSTER, 1, 1);
    cfg.blockDim = dim3(FPS_THREADS, 1, 1);
    cfg.dynamicSmemBytes = 0;
    cfg.stream = 0;
    cudaLaunchAttribute attrs[1];
    attrs[0].id = cudaLaunchAttributeClusterDimension;
    attrs[0].val.clusterDim.x = CLUSTER;
    attrs[0].val.clusterDim.y = 1;
    attrs[0].val.clusterDim.z = 1;
    cfg.attrs = attrs;
    cfg.numAttrs = 1;
    cudaLaunchKernelEx(&cfg, fps_kernel);

    nbr_kernel<<<(CLOUDS * MCENT * 32) / 256, 256>>>(out, out_size);
    sample_kernel<<<(CLOUDS * MCENT + 255) / 256, 256>>>(pos, out, out_size);
}

// round 13
// speedup vs baseline: 1.0501x; 1.0501x over previous
#include <cuda_runtime.h>
#include <cuda_bf16.h>

// ---------------------------------------------------------------------------
// Problem constants (fixed by the reference)
// ---------------------------------------------------------------------------
#define CLOUDS   4
#define NPTS     16384
#define MCENT    4096            // RATIO * NPTS
#define MAXNB    64
#define R2       0.0625f         // 0.25^2
#define CLUSTER  16              // nonportable cluster size
#define PTS_PER_CTA (NPTS / CLUSTER)   // 1024
#define FPS_THREADS 256
#define PPT      4               // points per thread
#define PAIRS    (PPT / 2)
#define NWARPS   (FPS_THREADS / 32)    // 8

#define OUT_XC   0                      // x_centers  [16384*3]
#define OUT_POS  (CLOUDS*MCENT*3)       // pos[idx]   [16384*3]
#define OUT_BAT  (CLOUDS*MCENT*6)       // batch[idx] [16384]

// Device scratch (no cudaMalloc allowed)
__device__ float g_pos6[(size_t)CLOUDS * NPTS * 8];  // padded to 8 floats/pt
__device__ int   g_idx[CLOUDS * MCENT];

// ---------------------------------------------------------------------------
// f32x2 helpers (bit-exact packed math)
// ---------------------------------------------------------------------------
__device__ __forceinline__ unsigned long long pack2(float lo, float hi) {
    unsigned long long r;
    asm("mov.b64 %0, {%1, %2};" : "=l"(r) : "f"(lo), "f"(hi));
    return r;
}
__device__ __forceinline__ void unpack2(unsigned long long v,
                                        float& lo, float& hi) {
    asm("mov.b64 {%0, %1}, %2;" : "=f"(lo), "=f"(hi) : "l"(v));
}
__device__ __forceinline__ unsigned long long fma2(unsigned long long a,
                                                   unsigned long long b,
                                                   unsigned long long c) {
    unsigned long long r;
    asm("fma.rn.f32x2 %0, %1, %2, %3;"
        : "=l"(r) : "l"(a), "l"(b), "l"(c));
    return r;
}
__device__ __forceinline__ unsigned long long mul2(unsigned long long a,
                                                   unsigned long long b) {
    unsigned long long r;
    asm("mul.rn.f32x2 %0, %1, %2;" : "=l"(r) : "l"(a), "l"(b));
    return r;
}

// ---------------------------------------------------------------------------
// 6-D squared distance (scalar form for the neighbor kernel).
// FMA left fold matches XLA:GPU contraction of sum((p-c)**2, axis=-1).
// ---------------------------------------------------------------------------
__device__ __forceinline__ float dist6(float p0, float p1, float p2,
                                       float p3, float p4, float p5,
                                       float c0, float c1, float c2,
                                       float c3, float c4, float c5) {
    float t, d;
    t = __fsub_rn(p0, c0); d = __fmul_rn(t, t);
    t = __fsub_rn(p1, c1); d = __fmaf_rn(t, t, d);
    t = __fsub_rn(p2, c2); d = __fmaf_rn(t, t, d);
    t = __fsub_rn(p3, c3); d = __fmaf_rn(t, t, d);
    t = __fsub_rn(p4, c4); d = __fmaf_rn(t, t, d);
    t = __fsub_rn(p5, c5); d = __fmaf_rn(t, t, d);
    return d;
}

__device__ __forceinline__ unsigned redux_max_u32(unsigned v, unsigned mask) {
    unsigned r;
    asm("redux.sync.max.u32 %0, %1, %2;" : "=r"(r) : "r"(v), "r"(mask));
    return r;
}

// ---------------------------------------------------------------------------
// Kernel A: build padded pos6 = [x0 x1 x2 p0 p1 p2 0 0] per point
// ---------------------------------------------------------------------------
__global__ void prep_kernel(const float* __restrict__ x,
                            const float* __restrict__ pos) {
    int i = blockIdx.x * blockDim.x + threadIdx.x;
    if (i >= CLOUDS * NPTS) return;
    float4 r0 = make_float4(x[3 * i], x[3 * i + 1], x[3 * i + 2], pos[3 * i]);
    float4 r1 = make_float4(pos[3 * i + 1], pos[3 * i + 2], 0.f, 0.f);
    float4* dst = reinterpret_cast<float4*>(g_pos6);
    dst[2 * i] = r0;
    dst[2 * i + 1] = r1;
}

// ---------------------------------------------------------------------------
// Kernel B: FPS v10 = v8 champion + pair-packed SoA f32x2 distance math.
// 16-CTA cluster per cloud, 256 thr/CTA, 4 pts/thread.
// 32 lanes of warp0 send half-records; warp0 alone waits; bar releases CTA;
// all warps resolve candbuf in parallel.
// Candidate record = 8 u32: {keybits, cloud_idx, c0,c1,c2,c3,c4,c5}.
// ---------------------------------------------------------------------------
__global__ void __launch_bounds__(FPS_THREADS, 1)
fps_kernel() {
    __shared__ unsigned long long mbar[2];
    __shared__ uint4 candbuf[2][CLUSTER][2];   // [parity][sender rank][32B]
    __shared__ unsigned slotkey[NWARPS];       // per-warp winner keybits
    __shared__ uint4 slotc[NWARPS][2];         // per-warp winner record

    unsigned rank;
    asm("mov.u32 %0, %%cluster_ctarank;" : "=r"(rank));
    const int cloud = blockIdx.x / CLUSTER;
    const int tid = threadIdx.x;
    const int wid = tid >> 5;
    const int lane = tid & 31;

    const float4* gp = reinterpret_cast<const float4*>(
        g_pos6 + (size_t)cloud * NPTS * 8);

    const int gbase = (int)rank * PTS_PER_CTA + tid * PPT;  // cloud-local

    // SoA pair packing: P[d][pr] = {dim d of pt 2pr, dim d of pt 2pr+1}
    unsigned long long P[6][PAIRS];
    float mind[PPT];
    const unsigned long long NEG1 = pack2(-1.0f, -1.0f);
#pragma unroll
    for (int pr = 0; pr < PAIRS; ++pr) {
        float4 e0 = gp[2 * (gbase + 2 * pr)],     e1 = gp[2 * (gbase + 2 * pr) + 1];
        float4 o0 = gp[2 * (gbase + 2 * pr + 1)], o1 = gp[2 * (gbase + 2 * pr + 1) + 1];
        P[0][pr] = pack2(e0.x, o0.x);
        P[1][pr] = pack2(e0.y, o0.y);
        P[2][pr] = pack2(e0.z, o0.z);
        P[3][pr] = pack2(e0.w, o0.w);
        P[4][pr] = pack2(e1.x, o1.x);
        P[5][pr] = pack2(e1.y, o1.y);
        mind[2 * pr] = __int_as_float(0x7f800000);
        mind[2 * pr + 1] = __int_as_float(0x7f800000);
    }

    // current winner coords; pick 0 = point 0 of the cloud
    float4 p0 = gp[0], p1 = gp[1];
    float w0 = p0.x, w1 = p0.y, w2 = p0.z, w3 = p0.w, w4 = p1.x, w5 = p1.y;

    if (tid == 0) {
        unsigned m0 = (unsigned)__cvta_generic_to_shared(&mbar[0]);
        unsigned m1 = (unsigned)__cvta_generic_to_shared(&mbar[1]);
        asm volatile("mbarrier.init.shared.b64 [%0], 1;" :: "r"(m0) : "memory");
        asm volatile("mbarrier.init.shared.b64 [%0], 1;" :: "r"(m1) : "memory");
        asm volatile("fence.mbarrier_init.release.cluster;" ::: "memory");
        if (rank == 0) g_idx[cloud * MCENT] = cloud * NPTS;
    }
    __syncthreads();
    // make mbarrier init visible cluster-wide before any peer st.async
    asm volatile("barrier.cluster.arrive.aligned;" ::: "memory");
    asm volatile("barrier.cluster.wait.aligned;"   ::: "memory");

    // loop-invariant peer addresses: lane i -> CTA i>>1, half (i&1)*16B
    unsigned dr0 = 0, dr1 = 0, mr0 = 0, mr1 = 0;
    if (wid == 0) {
        unsigned dst = (unsigned)(lane >> 1);
        unsigned half = (unsigned)(lane & 1) * 16u;
        unsigned dl0 = (unsigned)__cvta_generic_to_shared(&candbuf[0][rank][0]) + half;
        unsigned dl1 = (unsigned)__cvta_generic_to_shared(&candbuf[1][rank][0]) + half;
        unsigned ml0 = (unsigned)__cvta_generic_to_shared(&mbar[0]);
        unsigned ml1 = (unsigned)__cvta_generic_to_shared(&mbar[1]);
        asm("mapa.shared::cluster.u32 %0, %1, %2;" : "=r"(dr0) : "r"(dl0), "r"(dst));
        asm("mapa.shared::cluster.u32 %0, %1, %2;" : "=r"(dr1) : "r"(dl1), "r"(dst));
        asm("mapa.shared::cluster.u32 %0, %1, %2;" : "=r"(mr0) : "r"(ml0), "r"(dst));
        asm("mapa.shared::cluster.u32 %0, %1, %2;" : "=r"(mr1) : "r"(ml1), "r"(dst));
    }
    const unsigned mb0 = (unsigned)__cvta_generic_to_shared(&mbar[0]);
    const unsigned mb1 = (unsigned)__cvta_generic_to_shared(&mbar[1]);

    unsigned ph0 = 0, ph1 = 0;

#pragma unroll 1
    for (int k = 1; k < MCENT; ++k) {
        const int par = k & 1;
        if (tid == 0) {   // expected tx: 16 CTAs x 32 bytes
            asm volatile("mbarrier.arrive.expect_tx.shared.b64 _, [%0], %1;"
                         :: "r"(par ? mb1 : mb0), "r"(512u) : "memory");
        }
        // ---- packed-pair distances; thread-best (idx ascending, strict >) --
        const unsigned long long W0 = pack2(w0, w0);
        const unsigned long long W1 = pack2(w1, w1);
        const unsigned long long W2 = pack2(w2, w2);
        const unsigned long long W3 = pack2(w3, w3);
        const unsigned long long W4 = pack2(w4, w4);
        const unsigned long long W5 = pack2(w5, w5);
        unsigned bk = 0;
        unsigned bj = 0;
#pragma unroll
        for (int pr = 0; pr < PAIRS; ++pr) {
            unsigned long long T0 = fma2(W0, NEG1, P[0][pr]);
            unsigned long long T1 = fma2(W1, NEG1, P[1][pr]);
            unsigned long long T2 = fma2(W2, NEG1, P[2][pr]);
            unsigned long long T3 = fma2(W3, NEG1, P[3][pr]);
            unsigned long long T4 = fma2(W4, NEG1, P[4][pr]);
            unsigned long long T5 = fma2(W5, NEG1, P[5][pr]);
            unsigned long long D = mul2(T0, T0);
            D = fma2(T1, T1, D);
            D = fma2(T2, T2, D);
            D = fma2(T3, T3, D);
            D = fma2(T4, T4, D);
            D = fma2(T5, T5, D);
            float dlo, dhi;
            unpack2(D, dlo, dhi);
            mind[2 * pr] = fminf(mind[2 * pr], dlo);
            mind[2 * pr + 1] = fminf(mind[2 * pr + 1], dhi);
            unsigned k0 = __float_as_uint(mind[2 * pr]);
            if (k0 > bk) { bk = k0; bj = (unsigned)(2 * pr); }
            unsigned k1 = __float_as_uint(mind[2 * pr + 1]);
            if (k1 > bk) { bk = k1; bj = (unsigned)(2 * pr + 1); }
        }

        // ---- warp argmax: redux + ballot (lowest lane = lowest idx) ----
        unsigned m = redux_max_u32(bk, 0xffffffffu);
        unsigned bal = __ballot_sync(0xffffffffu, bk == m);
        if (lane == __ffs(bal) - 1) {
            // extract winning point's coords from SoA registers
            int pr = (int)(bj >> 1);
            bool hi = (bj & 1u) != 0;
            float c[6];
#pragma unroll
            for (int d = 0; d < 6; ++d) {
                float lo, h;
                unsigned long long v = P[d][0];
#pragma unroll
                for (int q = 1; q < PAIRS; ++q)
                    if (q == pr) v = P[d][q];
                unpack2(v, lo, h);
                c[d] = hi ? h : lo;
            }
            slotkey[wid] = m;
            slotc[wid][0] = make_uint4(m, (unsigned)(gbase + (int)bj),
                                       __float_as_uint(c[0]),
                                       __float_as_uint(c[1]));
            slotc[wid][1] = make_uint4(__float_as_uint(c[2]),
                                       __float_as_uint(c[3]),
                                       __float_as_uint(c[4]),
                                       __float_as_uint(c[5]));
        }
        __syncthreads();   // bar(1): 8 slots ready

        if (wid == 0) {
            // ---- CTA argmax over 8 warp slots (slot order = idx order) ----
            unsigned kw = slotkey[lane & (NWARPS - 1)];
            unsigned M = redux_max_u32(kw, 0xffffffffu);
            unsigned bb = __ballot_sync(0xffffffffu, kw == M);
            int s = __ffs(bb) - 1;          // lowest lane = lowest warp
            // all 32 lanes send one 16B half-record: lane i -> CTA i>>1
            {
                const unsigned long long* src =
                    reinterpret_cast<const unsigned long long*>(&slotc[s][0]);
                unsigned h = (unsigned)(lane & 1) * 2u;
                unsigned long long qa = src[h], qb = src[h + 1];
                unsigned dr = par ? dr1 : dr0;
                unsigned mr = par ? mr1 : mr0;
                asm volatile(
                    "st.async.shared::cluster.mbarrier::complete_tx::bytes.v2.b64 [%0], {%1, %2}, [%3];"
                    :: "r"(dr), "l"(qa), "l"(qb), "r"(mr) : "memory");
            }
            // ---- warp0 alone waits for the 16 candidates ----
            unsigned mb = par ? mb1 : mb0;
            unsigned ph = par ? ph1 : ph0;
            unsigned done;
            do {
                asm volatile(
                    "{ .reg .pred p;\n\t"
                    "mbarrier.try_wait.parity.acquire.cta.shared::cta.b64 p, [%1], %2, 0x989680;\n\t"
                    "selp.b32 %0, 1, 0, p; }"
                    : "=r"(done) : "r"(mb), "r"(ph) : "memory");
            } while (!done);
        }
        if (par) ph1 ^= 1; else ph0 ^= 1;
        __syncthreads();   // bar(2): candbuf complete for everyone

        // ---- ALL warps resolve cluster winner into registers (parallel) ----
        {
            unsigned kc = candbuf[par][lane & (CLUSTER - 1)][0].x;
            unsigned M2 = redux_max_u32(kc, 0xffffffffu);
            unsigned b2 = __ballot_sync(0xffffffffu, kc == M2);
            int s2 = __ffs(b2) - 1;          // lowest lane -> lowest rank
            uint4 r0 = candbuf[par][s2][0];
            uint4 r1 = candbuf[par][s2][1];
            w0 = __uint_as_float(r0.z); w1 = __uint_as_float(r0.w);
            w2 = __uint_as_float(r1.x); w3 = __uint_as_float(r1.y);
            w4 = __uint_as_float(r1.z); w5 = __uint_as_float(r1.w);
            if (rank == 0 && tid == 0)
                g_idx[cloud * MCENT + k] = cloud * NPTS + (int)r0.y;
        }
    }
}

// ---------------------------------------------------------------------------
// Kernel C: radius neighbors + mean.  One warp per center; ordered first-64
// take via ballot so capping matches top_k-on-index semantics exactly.
// ---------------------------------------------------------------------------
__global__ void __launch_bounds__(256)
nbr_kernel(float* __restrict__ out, int out_size) {
    int w = (blockIdx.x * blockDim.x + threadIdx.x) >> 5;
    int lane = threadIdx.x & 31;
    if (w >= CLOUDS * MCENT) return;
    int cloud = w >> 12;                 // 4096 centers per cloud
    int g = g_idx[w];
    int lc = g - cloud * NPTS;

    const float4* gp = reinterpret_cast<const float4*>(
        g_pos6 + (size_t)cloud * NPTS * 8);
    float4 c0 = gp[2 * lc], c1 = gp[2 * lc + 1];

    float sx = 0.f, sy = 0.f, sz = 0.f;
    int cnt = 0;
    for (int base = 0; base < NPTS; base += 32) {
        int i = base + lane;
        float4 a0 = gp[2 * i], a1 = gp[2 * i + 1];
        float d = dist6(a0.x, a0.y, a0.z, a0.w, a1.x, a1.y,
                        c0.x, c0.y, c0.z, c0.w, c1.x, c1.y);
        bool pred = (d <= R2);
        unsigned mask = __ballot_sync(0xffffffffu, pred);
        int need = MAXNB - cnt;
        int rk = __popc(mask & ((1u << lane) - 1u));
        if (pred && rk < need) { sx += a0.x; sy += a0.y; sz += a0.z; }
        int c = __popc(mask);
        cnt += (c < need) ? c : need;
        if (cnt >= MAXNB) break;         // warp-uniform
    }
#pragma unroll
    for (int s = 16; s > 0; s >>= 1) {
        sx += __shfl_down_sync(0xffffffffu, sx, s);
        sy += __shfl_down_sync(0xffffffffu, sy, s);
        sz += __shfl_down_sync(0xffffffffu, sz, s);
    }
    if (lane == 0) {
        float c = (float)cnt;            // self always in radius -> cnt >= 1
        if (OUT_XC + w * 3 + 2 < out_size) {
            out[OUT_XC + w * 3 + 0] = sx / c;
            out[OUT_XC + w * 3 + 1] = sy / c;
            out[OUT_XC + w * 3 + 2] = sz / c;
        }
    }
}

// ---------------------------------------------------------------------------
// Kernel D: gather pos[idx] and batch[idx]
// ---------------------------------------------------------------------------
__global__ void sample_kernel(const float* __restrict__ pos,
                              float* __restrict__ out, int out_size) {
    int c = blockIdx.x * blockDim.x + threadIdx.x;
    if (c >= CLOUDS * MCENT) return;
    int g = g_idx[c];
    if (OUT_POS + c * 3 + 2 < out_size) {
        out[OUT_POS + c * 3 + 0] = pos[3 * g + 0];
        out[OUT_POS + c * 3 + 1] = pos[3 * g + 1];
        out[OUT_POS + c * 3 + 2] = pos[3 * g + 2];
    }
    if (OUT_BAT + c < out_size)
        out[OUT_BAT + c] = (float)(g >> 14);   // batch id = g / NPTS
}

// ---------------------------------------------------------------------------
extern "C" void kernel_launch(void* const* d_in, const int* in_sizes, int n_in,
                              void* d_out, int out_size) {
    const float* x   = (const float*)d_in[0];
    const float* pos = (const float*)d_in[1];
    float* out = (float*)d_out;

    prep_kernel<<<(CLOUDS * NPTS + 255) / 256, 256>>>(x, pos);

    // FPS: 16-CTA clusters (nonportable size) via cudaLaunchKernelEx
    cudaFuncSetAttribute(fps_kernel,
                         cudaFuncAttributeNonPortableClusterSizeAllowed, 1);
    cudaLaunchConfig_t cfg = {};
    cfg.gridDim = dim3(CLOUDS * CLUSTER, 1, 1);
    cfg.blockDim = dim3(FPS_THREADS, 1, 1);
    cfg.dynamicSmemBytes = 0;
    cfg.stream = 0;
    cudaLaunchAttribute attrs[1];
    attrs[0].id = cudaLaunchAttributeClusterDimension;
    attrs[0].val.clusterDim.x = CLUSTER;
    attrs[0].val.clusterDim.y = 1;
    attrs[0].val.clusterDim.z = 1;
    cfg.attrs = attrs;
    cfg.numAttrs = 1;
    cudaLaunchKernelEx(&cfg, fps_kernel);

    nbr_kernel<<<(CLOUDS * MCENT * 32) / 256, 256>>>(out, out_size);
    sample_kernel<<<(CLOUDS * MCENT + 255) / 256, 256>>>(pos, out, out_size);
}